// round 8
// baseline (speedup 1.0000x reference)
#include <cuda_runtime.h>
#include <cuda_bf16.h>

#define WARPS_PER_BLOCK 8
#define NTHR (32 * WARPS_PER_BLOCK)

__device__ __forceinline__ float clip01(float v) { return fminf(fmaxf(v, 0.0f), 1.0f); }

__device__ __forceinline__ void process_bq(
    int bq, int lane,
    const float* __restrict__ G, const float* __restrict__ H,
    const float* __restrict__ C, const float* __restrict__ W,
    float* __restrict__ out)
{
    const size_t base = (size_t)bq * 4096;
    const float4* h4 = reinterpret_cast<const float4*>(H + base);
    const float4* g4 = reinterpret_cast<const float4*>(G + base);

    // Per-lane layout: float4 slot s = m*32 + lane (m = 0..31);
    // element idx = s*4+k; row = s>>4 = 2*m + (lane>>4); col = (lane&15)*4 + k.
    float hmax = -1e30f;
    unsigned colnib = 0;              // 4 col bits (cols fixed per lane)
    unsigned rml = 0, rmh = 0;        // row mask lo/hi
    float gmax = -1e30f; int gidx = 0;

    // ---- head: max + >=0.5 masks (conf_head = clip01(max); clip monotone) ----
#pragma unroll
    for (int b = 0; b < 4; b++) {
        float4 v[8];
#pragma unroll
        for (int i = 0; i < 8; i++) v[i] = h4[(b * 8 + i) * 32 + lane];
#pragma unroll
        for (int i = 0; i < 8; i++) {
            const int m = b * 8 + i;
            float a[4] = {v[i].x, v[i].y, v[i].z, v[i].w};
            bool any5 = false;
#pragma unroll
            for (int k = 0; k < 4; k++) {
                hmax = fmaxf(hmax, a[k]);
                if (a[k] >= 0.5f) { colnib |= 1u << k; any5 = true; }
            }
            if (any5) {
                int row = 2 * m + (lane >> 4);
                if (row < 32) rml |= 1u << row; else rmh |= 1u << (row - 32);
            }
        }
    }

    // ---- gaze: (val, idx) argmax; clip applied to scalar max below (inputs
    //      in [0,1) so per-element clip is identity; strict > keeps
    //      first-index semantics) ----
#pragma unroll
    for (int b = 0; b < 4; b++) {
        float4 v[8];
#pragma unroll
        for (int i = 0; i < 8; i++) v[i] = g4[(b * 8 + i) * 32 + lane];
#pragma unroll
        for (int i = 0; i < 8; i++) {
            const int m = b * 8 + i;
            float a[4] = {v[i].x, v[i].y, v[i].z, v[i].w};
#pragma unroll
            for (int k = 0; k < 4; k++) {
                int idx = (m * 32 + lane) * 4 + k;
                if (a[k] > gmax) { gmax = a[k]; gidx = idx; }
            }
        }
    }

    // ---- warp-wide masks via REDUX (uniform result in all lanes) ----
    const unsigned c15 = lane & 15;
    unsigned mcl = (c15 < 8)  ? (colnib << (c15 * 4))       : 0u;
    unsigned mch = (c15 >= 8) ? (colnib << ((c15 - 8) * 4)) : 0u;
    const unsigned cl = __reduce_or_sync(0xffffffffu, mcl);
    const unsigned ch = __reduce_or_sync(0xffffffffu, mch);
    const unsigned rl = __reduce_or_sync(0xffffffffu, rml);
    const unsigned rh = __reduce_or_sync(0xffffffffu, rmh);

    // ---- butterfly reductions: every lane ends with the warp result ----
#pragma unroll
    for (int o = 16; o; o >>= 1) {
        hmax = fmaxf(hmax, __shfl_xor_sync(0xffffffffu, hmax, o));
        float gv2 = __shfl_xor_sync(0xffffffffu, gmax, o);
        int   gi2 = __shfl_xor_sync(0xffffffffu, gidx, o);
        if (gv2 > gmax || (gv2 == gmax && gi2 < gidx)) { gmax = gv2; gidx = gi2; }
    }

    // ---- bbox (rare fallback: no pixel >= 0.5 -> head peak, warp-uniform) ----
    int x1, x2, y1, y2;
    if ((cl | ch) != 0u) {
        unsigned long long cm = ((unsigned long long)ch << 32) | cl;
        unsigned long long rm = ((unsigned long long)rh << 32) | rl;
        x1 = __ffsll((long long)cm) - 1;
        x2 = 64 - __clzll((long long)cm);
        y1 = __ffsll((long long)rm) - 1;
        y2 = 64 - __clzll((long long)rm);
    } else {
        float pv = -1e30f; int pi = 0;
#pragma unroll 4
        for (int m = 0; m < 32; m++) {
            float4 v = h4[m * 32 + lane];          // reload (L2-hot)
            float a[4] = {v.x, v.y, v.z, v.w};
#pragma unroll
            for (int k = 0; k < 4; k++) {
                float hv = clip01(a[k]);
                int idx = (m * 32 + lane) * 4 + k;
                if (hv > pv) { pv = hv; pi = idx; }
            }
        }
#pragma unroll
        for (int o = 16; o; o >>= 1) {
            float v2 = __shfl_xor_sync(0xffffffffu, pv, o);
            int   i2 = __shfl_xor_sync(0xffffffffu, pi, o);
            if (v2 > pv || (v2 == pv && i2 < pi)) { pv = v2; pi = i2; }
        }
        int px = pi & 63, py = pi >> 6;
        x1 = px; x2 = px + 1; y1 = py; y2 = py + 1;
    }

    // ---- epilogue (warp-uniform; 10 connect samples on lanes 0-9) ----
    const float conf_head = clip01(hmax);
    const float conf_gaze = clip01(gmax);
    const float gpx = fminf(fmaxf((float)(gidx & 63), 0.0f), 63.0f);
    const float gpy = fminf(fmaxf((float)(gidx >> 6), 0.0f), 63.0f);
    const float cx = (float)(x1 + x2) * 0.5f;
    const float cy = (float)(y1 + y2) * 0.5f;
    // jnp.round == round-half-to-even == rintf (cx/cy hit .5 exactly)
    const float hcx = fminf(fmaxf(rintf(cx), 0.0f), 63.0f);
    const float hcy = fminf(fmaxf(rintf(cy), 0.0f), 63.0f);
    const float dx = gpx - hcx, dy = gpy - hcy;
    const float stx = dx / 9.0f, sty = dy / 9.0f;   // linspace step, num=10

    float samp = 0.0f;
    if (lane < 10) {
        int xi = (int)rintf(hcx + (float)lane * stx);
        int yi = (int)rintf(hcy + (float)lane * sty);
        samp = clip01(__ldg(C + base + yi * 64 + xi));
    }
#pragma unroll
    for (int o = 16; o; o >>= 1) samp += __shfl_xor_sync(0xffffffffu, samp, o);

    if (lane == 0) {
        float norm = sqrtf(dx * dx + dy * dy);
        float dp = fminf(32.0f / norm - 1.0f, 0.0f);  // norm==0 -> +inf -> 0
        float score = samp / 10.0f + dp;
        float watch = W[bq];
        float r = (watch > 0.5f)
                ? (conf_head + (1.0f - conf_gaze) - score)
                : (conf_head + conf_gaze + score);
        out[bq] = r / 3.0f;
    }
}

__global__ __launch_bounds__(NTHR, 4)
void gotd_eval_kernel(const float* __restrict__ G,   // gaze heatmaps   [n,64,64]
                      const float* __restrict__ H,   // head heatmaps   [n,64,64]
                      const float* __restrict__ C,   // connect heatmaps[n,64,64]
                      const float* __restrict__ W,   // watch_outside   [n]
                      float* __restrict__ out, int n)
{
    const int warp = threadIdx.x >> 5;
    const int lane = threadIdx.x & 31;
    const int w = blockIdx.x * WARPS_PER_BLOCK + warp;
    const int bq0 = 2 * w;
    if (bq0 >= n) return;
    const int bq1 = bq0 + 1;

    // ---- register-free DRAM concurrency: prefetch bq1's tiles into L2
    //      while bq0 is being processed. 8 insts x 32 lanes x 128B = 32KB.
    //      Use distance ~1 bq (~1us, ~6MB L2 churn) so no eviction-before-use.
    if (bq1 < n) {
        const char* hb = reinterpret_cast<const char*>(H + (size_t)bq1 * 4096);
        const char* gb = reinterpret_cast<const char*>(G + (size_t)bq1 * 4096);
#pragma unroll
        for (int i = 0; i < 4; i++) {
            asm volatile("prefetch.global.L2 [%0];" :: "l"(hb + (i * 32 + lane) * 128));
            asm volatile("prefetch.global.L2 [%0];" :: "l"(gb + (i * 32 + lane) * 128));
        }
    }

    process_bq(bq0, lane, G, H, C, W, out);
    if (bq1 < n) process_bq(bq1, lane, G, H, C, W, out);
}

extern "C" void kernel_launch(void* const* d_in, const int* in_sizes, int n_in,
                              void* d_out, int out_size) {
    const float* G = (const float*)d_in[0];  // pred_gaze_heatmap
    const float* H = (const float*)d_in[1];  // pred_head_heatmap
    const float* C = (const float*)d_in[2];  // pred_connect_heatmap
    const float* W = (const float*)d_in[3];  // pred_gaze_watch_outside
    float* out = (float*)d_out;
    int n = in_sizes[3];                     // B*Q = 8192
    int nw = (n + 1) / 2;                    // one warp per bq-pair
    int grid = (nw + WARPS_PER_BLOCK - 1) / WARPS_PER_BLOCK;   // 512
    gotd_eval_kernel<<<grid, NTHR>>>(G, H, C, W, out, n);
}

// round 10
// speedup vs baseline: 1.2709x; 1.2709x over previous
#include <cuda_runtime.h>
#include <cuda_bf16.h>
#include <cstdint>

#define WARPS_PER_BLOCK 8
#define NTHR (32 * WARPS_PER_BLOCK)
#define CH_SLOTS 4                 // float4 slots per lane per chunk
#define NCHUNK 16                  // 8 head + 8 gaze chunks per bq
#define NBUF 3                     // smem ring depth per warp

__device__ __forceinline__ float clip01(float v) { return fminf(fmaxf(v, 0.0f), 1.0f); }

__device__ __forceinline__ void cp16(unsigned int saddr, const void* gptr) {
    asm volatile("cp.async.cg.shared.global [%0], [%1], 16;" :: "r"(saddr), "l"(gptr));
}
#define CP_COMMIT() asm volatile("cp.async.commit_group;" ::: "memory")
#define CP_WAIT1()  asm volatile("cp.async.wait_group 1;" ::: "memory")
#define CP_WAIT0()  asm volatile("cp.async.wait_group 0;" ::: "memory")

__global__ __launch_bounds__(NTHR, 4)
void gotd_eval_kernel(const float* __restrict__ G,   // gaze heatmaps   [n,64,64]
                      const float* __restrict__ H,   // head heatmaps   [n,64,64]
                      const float* __restrict__ C,   // connect heatmaps[n,64,64]
                      const float* __restrict__ W,   // watch_outside   [n]
                      float* __restrict__ out, int n)
{
    // Ring: [warp][buf][slot][lane] float4 = 8*3*4*32*16 = 48 KB (static).
    __shared__ float4 sbuf[WARPS_PER_BLOCK * NBUF * CH_SLOTS * 32];

    const int warp = threadIdx.x >> 5;
    const int lane = threadIdx.x & 31;
    const int bq = blockIdx.x * WARPS_PER_BLOCK + warp;
    if (bq >= n) return;

    const size_t base = (size_t)bq * 4096;
    const float4* h4 = reinterpret_cast<const float4*>(H + base);
    const float4* g4 = reinterpret_cast<const float4*>(G + base);

    float4* wbuf = &sbuf[(warp * NBUF) * CH_SLOTS * 32];
    const unsigned int sbase = (unsigned int)__cvta_generic_to_shared(wbuf);

    // Chunk c: source = (c<8 ? head batch c : gaze batch c-8), 4 float4/lane.
    // Lane copies ONLY its own slots (s = i*32+lane) and later reads only
    // those -> per-thread wait_group is sufficient ordering, no __syncwarp.
    auto issue_chunk = [&](int c, int buf) {
        const float4* src = (c < 8) ? (h4 + (c * CH_SLOTS) * 32)
                                    : (g4 + ((c - 8) * CH_SLOTS) * 32);
        unsigned int sb = sbase + (unsigned int)(buf * CH_SLOTS * 32 + lane) * 16u;
#pragma unroll
        for (int i = 0; i < CH_SLOTS; i++)
            cp16(sb + (unsigned int)(i * 32) * 16u, src + i * 32 + lane);
        CP_COMMIT();
    };

    issue_chunk(0, 0);
    issue_chunk(1, 1);

    // Per-lane layout (as R3): slot s = m*32+lane; elem idx = s*4+k;
    // row = 2*m + (lane>>4); col = (lane&15)*4 + k.
    float hmax = -1e30f;
    unsigned colnib = 0;
    unsigned rml = 0, rmh = 0;
    float gmax = -1e30f; int gidx = 0;

#pragma unroll
    for (int c = 0; c < NCHUNK; c++) {
        if (c < NCHUNK - 1) { CP_WAIT1(); } else { CP_WAIT0(); }

        const float4* buf = wbuf + (c % NBUF) * CH_SLOTS * 32;
#pragma unroll
        for (int i = 0; i < CH_SLOTS; i++) {
            float4 v = buf[i * 32 + lane];
            float a[4] = {v.x, v.y, v.z, v.w};
            if (c < 8) {
                const int m = c * CH_SLOTS + i;
                bool any5 = false;
#pragma unroll
                for (int k = 0; k < 4; k++) {
                    hmax = fmaxf(hmax, a[k]);
                    if (a[k] >= 0.5f) { colnib |= 1u << k; any5 = true; }
                }
                if (any5) {
                    int row = 2 * m + (lane >> 4);
                    if (row < 32) rml |= 1u << row; else rmh |= 1u << (row - 32);
                }
            } else {
                const int m = (c - 8) * CH_SLOTS + i;
#pragma unroll
                for (int k = 0; k < 4; k++) {
                    // raw-value argmax; clip01 on the scalar max below (inputs
                    // in [0,1): per-element clip is identity; strict > keeps
                    // first-index semantics).
                    int idx = (m * 32 + lane) * 4 + k;
                    if (a[k] > gmax) { gmax = a[k]; gidx = idx; }
                }
            }
        }

        if (c + 2 < NCHUNK) issue_chunk(c + 2, (c + 2) % NBUF);
    }

    // ---- warp-wide masks via REDUX (uniform result in all lanes) ----
    const unsigned c15 = lane & 15;
    unsigned mcl = (c15 < 8)  ? (colnib << (c15 * 4))       : 0u;
    unsigned mch = (c15 >= 8) ? (colnib << ((c15 - 8) * 4)) : 0u;
    const unsigned cl = __reduce_or_sync(0xffffffffu, mcl);
    const unsigned ch = __reduce_or_sync(0xffffffffu, mch);
    const unsigned rl = __reduce_or_sync(0xffffffffu, rml);
    const unsigned rh = __reduce_or_sync(0xffffffffu, rmh);

    // ---- butterfly reductions: every lane ends with the warp result ----
#pragma unroll
    for (int o = 16; o; o >>= 1) {
        hmax = fmaxf(hmax, __shfl_xor_sync(0xffffffffu, hmax, o));
        float gv2 = __shfl_xor_sync(0xffffffffu, gmax, o);
        int   gi2 = __shfl_xor_sync(0xffffffffu, gidx, o);
        if (gv2 > gmax || (gv2 == gmax && gi2 < gidx)) { gmax = gv2; gidx = gi2; }
    }

    // ---- bbox (rare fallback: no pixel >= 0.5 -> head peak, warp-uniform) ----
    int x1, x2, y1, y2;
    if ((cl | ch) != 0u) {
        unsigned long long cm = ((unsigned long long)ch << 32) | cl;
        unsigned long long rm = ((unsigned long long)rh << 32) | rl;
        x1 = __ffsll((long long)cm) - 1;
        x2 = 64 - __clzll((long long)cm);
        y1 = __ffsll((long long)rm) - 1;
        y2 = 64 - __clzll((long long)rm);
    } else {
        float pv = -1e30f; int pi = 0;
#pragma unroll 4
        for (int m = 0; m < 32; m++) {
            float4 v = h4[m * 32 + lane];          // rare reload (L2-hot)
            float a[4] = {v.x, v.y, v.z, v.w};
#pragma unroll
            for (int k = 0; k < 4; k++) {
                float hv = clip01(a[k]);
                int idx = (m * 32 + lane) * 4 + k;
                if (hv > pv) { pv = hv; pi = idx; }
            }
        }
#pragma unroll
        for (int o = 16; o; o >>= 1) {
            float v2 = __shfl_xor_sync(0xffffffffu, pv, o);
            int   i2 = __shfl_xor_sync(0xffffffffu, pi, o);
            if (v2 > pv || (v2 == pv && i2 < pi)) { pv = v2; pi = i2; }
        }
        int px = pi & 63, py = pi >> 6;
        x1 = px; x2 = px + 1; y1 = py; y2 = py + 1;
    }

    // ---- epilogue (warp-uniform; 10 connect samples on lanes 0-9) ----
    const float conf_head = clip01(hmax);
    const float conf_gaze = clip01(gmax);
    const float gpx = fminf(fmaxf((float)(gidx & 63), 0.0f), 63.0f);
    const float gpy = fminf(fmaxf((float)(gidx >> 6), 0.0f), 63.0f);
    const float cx = (float)(x1 + x2) * 0.5f;
    const float cy = (float)(y1 + y2) * 0.5f;
    // jnp.round == round-half-to-even == rintf (cx/cy hit .5 exactly)
    const float hcx = fminf(fmaxf(rintf(cx), 0.0f), 63.0f);
    const float hcy = fminf(fmaxf(rintf(cy), 0.0f), 63.0f);
    const float dx = gpx - hcx, dy = gpy - hcy;
    const float stx = dx / 9.0f, sty = dy / 9.0f;   // linspace step, num=10

    float samp = 0.0f;
    if (lane < 10) {
        int xi = (int)rintf(hcx + (float)lane * stx);
        int yi = (int)rintf(hcy + (float)lane * sty);
        samp = clip01(__ldg(C + base + yi * 64 + xi));
    }
#pragma unroll
    for (int o = 16; o; o >>= 1) samp += __shfl_xor_sync(0xffffffffu, samp, o);

    if (lane == 0) {
        float norm = sqrtf(dx * dx + dy * dy);
        float dp = fminf(32.0f / norm - 1.0f, 0.0f);  // norm==0 -> +inf -> 0
        float score = samp / 10.0f + dp;
        float watch = W[bq];
        float r = (watch > 0.5f)
                ? (conf_head + (1.0f - conf_gaze) - score)
                : (conf_head + conf_gaze + score);
        out[bq] = r / 3.0f;
    }
}

extern "C" void kernel_launch(void* const* d_in, const int* in_sizes, int n_in,
                              void* d_out, int out_size) {
    const float* G = (const float*)d_in[0];  // pred_gaze_heatmap
    const float* H = (const float*)d_in[1];  // pred_head_heatmap
    const float* C = (const float*)d_in[2];  // pred_connect_heatmap
    const float* W = (const float*)d_in[3];  // pred_gaze_watch_outside
    float* out = (float*)d_out;
    int n = in_sizes[3];                     // B*Q = 8192
    int grid = (n + WARPS_PER_BLOCK - 1) / WARPS_PER_BLOCK;   // 1024
    gotd_eval_kernel<<<grid, NTHR>>>(G, H, C, W, out, n);
}

// round 11
// speedup vs baseline: 1.3974x; 1.0995x over previous
#include <cuda_runtime.h>
#include <cuda_bf16.h>
#include <cstdint>

#define WARPS_PER_BLOCK 4
#define NTHR (32 * WARPS_PER_BLOCK)
#define CHUNK_BYTES 4096
#define CHUNK_F4 256               // float4 per 4 KB chunk
#define NCHUNK 8                   // 4 head + 4 gaze per bq

__device__ __forceinline__ float clip01(float v) { return fminf(fmaxf(v, 0.0f), 1.0f); }

__device__ __forceinline__ void mbar_init(unsigned int mbar, unsigned int count) {
    asm volatile("mbarrier.init.shared.b64 [%0], %1;" :: "r"(mbar), "r"(count) : "memory");
}
__device__ __forceinline__ void tma_issue(unsigned int dst, const void* src, unsigned int mbar) {
    asm volatile("mbarrier.arrive.expect_tx.shared.b64 _, [%0], %1;"
                 :: "r"(mbar), "r"((unsigned int)CHUNK_BYTES) : "memory");
    asm volatile("cp.async.bulk.shared::cluster.global.mbarrier::complete_tx::bytes "
                 "[%0], [%1], %2, [%3];"
                 :: "r"(dst), "l"(src), "r"((unsigned int)CHUNK_BYTES), "r"(mbar) : "memory");
}
__device__ __forceinline__ void mbar_wait(unsigned int mbar, unsigned int parity) {
    unsigned int done;
    asm volatile("{\n\t.reg .pred p;\n\t"
                 "mbarrier.try_wait.parity.acquire.cta.shared::cta.b64 p, [%1], %2;\n\t"
                 "selp.b32 %0, 1, 0, p;\n\t}"
                 : "=r"(done) : "r"(mbar), "r"(parity) : "memory");
    while (!done) {
        asm volatile("{\n\t.reg .pred p;\n\t"
                     "mbarrier.try_wait.parity.acquire.cta.shared::cta.b64 p, [%1], %2;\n\t"
                     "selp.b32 %0, 1, 0, p;\n\t}"
                     : "=r"(done) : "r"(mbar), "r"(parity) : "memory");
    }
}

__global__ __launch_bounds__(NTHR)
void gotd_eval_kernel(const float* __restrict__ G,   // gaze heatmaps   [n,64,64]
                      const float* __restrict__ H,   // head heatmaps   [n,64,64]
                      const float* __restrict__ C,   // connect heatmaps[n,64,64]
                      const float* __restrict__ W,   // watch_outside   [n]
                      float* __restrict__ out, int n)
{
    // [warp][buf][256 float4] = 4*2*4KB = 32 KB; + per-warp mbarrier pair.
    __shared__ float4 sbuf[WARPS_PER_BLOCK * 2 * CHUNK_F4];
    __shared__ unsigned long long smbar[WARPS_PER_BLOCK * 2];

    const int warp = threadIdx.x >> 5;
    const int lane = threadIdx.x & 31;
    const int bq = blockIdx.x * WARPS_PER_BLOCK + warp;

    float4* wbuf = &sbuf[warp * 2 * CHUNK_F4];
    const unsigned int sb0 = (unsigned int)__cvta_generic_to_shared(wbuf);
    const unsigned int sb1 = sb0 + CHUNK_BYTES;
    const unsigned int mb0 = (unsigned int)__cvta_generic_to_shared(&smbar[warp * 2]);
    const unsigned int mb1 = mb0 + 8;

    // Per-warp init: no cross-warp coupling anywhere, so no __syncthreads.
    if (lane == 0) {
        mbar_init(mb0, 1);
        mbar_init(mb1, 1);
        asm volatile("fence.proxy.async.shared::cta;" ::: "memory");
    }
    __syncwarp();
    if (bq >= n) return;

    const size_t base = (size_t)bq * 4096;
    const char* hsrc = reinterpret_cast<const char*>(H + base);
    const char* gsrc = reinterpret_cast<const char*>(G + base);

    // Chunk c: c<4 -> head bytes [c*4K,(c+1)*4K), else gaze [(c-4)*4K,...).
    auto chunk_src = [&](int c) -> const char* {
        return (c < 4) ? hsrc + c * CHUNK_BYTES : gsrc + (c - 4) * CHUNK_BYTES;
    };

    if (lane == 0) {
        tma_issue(sb0, chunk_src(0), mb0);
        tma_issue(sb1, chunk_src(1), mb1);
    }

    // Per-lane layout (as R3): global slot s = m*32+lane; elem idx = s*4+k;
    // row = 2*m + (lane>>4); col = (lane&15)*4+k. Chunk c holds m in [8c',8c'+8).
    float hmax = -1e30f;
    unsigned colnib = 0;
    unsigned rml = 0, rmh = 0;
    float gmax = -1e30f; int gidx = 0;

#pragma unroll
    for (int c = 0; c < NCHUNK; c++) {
        const unsigned int mb = (c & 1) ? mb1 : mb0;
        const float4* buf = wbuf + (c & 1) * CHUNK_F4;
        mbar_wait(mb, (c >> 1) & 1);           // uses of a buffer: parity 0,1,0,1

        float4 v[8];
#pragma unroll
        for (int i = 0; i < 8; i++) v[i] = buf[i * 32 + lane];

        if (c < 4) {
#pragma unroll
            for (int i = 0; i < 8; i++) {
                const int m = c * 8 + i;
                float a[4] = {v[i].x, v[i].y, v[i].z, v[i].w};
                bool any5 = false;
#pragma unroll
                for (int k = 0; k < 4; k++) {
                    hmax = fmaxf(hmax, a[k]);
                    if (a[k] >= 0.5f) { colnib |= 1u << k; any5 = true; }
                }
                if (any5) {
                    int row = 2 * m + (lane >> 4);
                    if (row < 32) rml |= 1u << row; else rmh |= 1u << (row - 32);
                }
            }
        } else {
#pragma unroll
            for (int i = 0; i < 8; i++) {
                const int m = (c - 4) * 8 + i;
                float a[4] = {v[i].x, v[i].y, v[i].z, v[i].w};
#pragma unroll
                for (int k = 0; k < 4; k++) {
                    // raw-value argmax; clip01 on scalar max below (inputs in
                    // [0,1): elementwise clip is identity; strict > keeps
                    // first-index semantics).
                    int idx = (m * 32 + lane) * 4 + k;
                    if (a[k] > gmax) { gmax = a[k]; gidx = idx; }
                }
            }
        }

        if (c + 2 < NCHUNK) {
            __syncwarp();                       // all lanes done reading buffer
            if (lane == 0) {
                asm volatile("fence.proxy.async.shared::cta;" ::: "memory");
                tma_issue((c & 1) ? sb1 : sb0, chunk_src(c + 2), mb);
            }
        }
    }

    // ---- warp-wide masks via REDUX (uniform result in all lanes) ----
    const unsigned c15 = lane & 15;
    unsigned mcl = (c15 < 8)  ? (colnib << (c15 * 4))       : 0u;
    unsigned mch = (c15 >= 8) ? (colnib << ((c15 - 8) * 4)) : 0u;
    const unsigned cl = __reduce_or_sync(0xffffffffu, mcl);
    const unsigned ch = __reduce_or_sync(0xffffffffu, mch);
    const unsigned rl = __reduce_or_sync(0xffffffffu, rml);
    const unsigned rh = __reduce_or_sync(0xffffffffu, rmh);

    // ---- butterfly reductions: every lane ends with the warp result ----
#pragma unroll
    for (int o = 16; o; o >>= 1) {
        hmax = fmaxf(hmax, __shfl_xor_sync(0xffffffffu, hmax, o));
        float gv2 = __shfl_xor_sync(0xffffffffu, gmax, o);
        int   gi2 = __shfl_xor_sync(0xffffffffu, gidx, o);
        if (gv2 > gmax || (gv2 == gmax && gi2 < gidx)) { gmax = gv2; gidx = gi2; }
    }

    // ---- bbox (rare fallback: no pixel >= 0.5 -> head peak, warp-uniform) ----
    int x1, x2, y1, y2;
    if ((cl | ch) != 0u) {
        unsigned long long cm = ((unsigned long long)ch << 32) | cl;
        unsigned long long rm = ((unsigned long long)rh << 32) | rl;
        x1 = __ffsll((long long)cm) - 1;
        x2 = 64 - __clzll((long long)cm);
        y1 = __ffsll((long long)rm) - 1;
        y2 = 64 - __clzll((long long)rm);
    } else {
        const float4* h4 = reinterpret_cast<const float4*>(H + base);
        float pv = -1e30f; int pi = 0;
#pragma unroll 4
        for (int m = 0; m < 32; m++) {
            float4 v = h4[m * 32 + lane];          // rare reload (L2-hot)
            float a[4] = {v.x, v.y, v.z, v.w};
#pragma unroll
            for (int k = 0; k < 4; k++) {
                float hv = clip01(a[k]);
                int idx = (m * 32 + lane) * 4 + k;
                if (hv > pv) { pv = hv; pi = idx; }
            }
        }
#pragma unroll
        for (int o = 16; o; o >>= 1) {
            float v2 = __shfl_xor_sync(0xffffffffu, pv, o);
            int   i2 = __shfl_xor_sync(0xffffffffu, pi, o);
            if (v2 > pv || (v2 == pv && i2 < pi)) { pv = v2; pi = i2; }
        }
        int px = pi & 63, py = pi >> 6;
        x1 = px; x2 = px + 1; y1 = py; y2 = py + 1;
    }

    // ---- epilogue (warp-uniform; 10 connect samples on lanes 0-9) ----
    const float conf_head = clip01(hmax);
    const float conf_gaze = clip01(gmax);
    const float gpx = fminf(fmaxf((float)(gidx & 63), 0.0f), 63.0f);
    const float gpy = fminf(fmaxf((float)(gidx >> 6), 0.0f), 63.0f);
    const float cx = (float)(x1 + x2) * 0.5f;
    const float cy = (float)(y1 + y2) * 0.5f;
    // jnp.round == round-half-to-even == rintf (cx/cy hit .5 exactly)
    const float hcx = fminf(fmaxf(rintf(cx), 0.0f), 63.0f);
    const float hcy = fminf(fmaxf(rintf(cy), 0.0f), 63.0f);
    const float dx = gpx - hcx, dy = gpy - hcy;
    const float stx = dx / 9.0f, sty = dy / 9.0f;   // linspace step, num=10

    float samp = 0.0f;
    if (lane < 10) {
        int xi = (int)rintf(hcx + (float)lane * stx);
        int yi = (int)rintf(hcy + (float)lane * sty);
        samp = clip01(__ldg(C + base + yi * 64 + xi));
    }
#pragma unroll
    for (int o = 16; o; o >>= 1) samp += __shfl_xor_sync(0xffffffffu, samp, o);

    if (lane == 0) {
        float norm = sqrtf(dx * dx + dy * dy);
        float dp = fminf(32.0f / norm - 1.0f, 0.0f);  // norm==0 -> +inf -> 0
        float score = samp / 10.0f + dp;
        float watch = W[bq];
        float r = (watch > 0.5f)
                ? (conf_head + (1.0f - conf_gaze) - score)
                : (conf_head + conf_gaze + score);
        out[bq] = r / 3.0f;
    }
}

extern "C" void kernel_launch(void* const* d_in, const int* in_sizes, int n_in,
                              void* d_out, int out_size) {
    const float* G = (const float*)d_in[0];  // pred_gaze_heatmap
    const float* H = (const float*)d_in[1];  // pred_head_heatmap
    const float* C = (const float*)d_in[2];  // pred_connect_heatmap
    const float* W = (const float*)d_in[3];  // pred_gaze_watch_outside
    float* out = (float*)d_out;
    int n = in_sizes[3];                     // B*Q = 8192
    int grid = (n + WARPS_PER_BLOCK - 1) / WARPS_PER_BLOCK;   // 2048
    gotd_eval_kernel<<<grid, NTHR>>>(G, H, C, W, out, n);
}